// round 2
// baseline (speedup 1.0000x reference)
#include <cuda_runtime.h>
#include <cuda_fp16.h>

typedef unsigned int u32;

// ---------------- static device scratch (sanctioned) ----------------
__device__ u32 g_amax_bits;
__device__ __align__(16) __half g_q [4096u * 4096u];   // quantized weight [N,K], fp16 (exact)
__device__ __align__(16) __half g_xh[8192u * 4096u];   // x in fp16, [M,K]

// ---------------- helpers ----------------
__device__ __forceinline__ u32 smem_u32(const void* p) {
    u32 a;
    asm("{ .reg .u64 t; cvta.to.shared.u64 t, %1; cvt.u32.u64 %0, t; }" : "=r"(a) : "l"(p));
    return a;
}
__device__ __forceinline__ void cp_async16(u32 s, const void* g) {
    asm volatile("cp.async.cg.shared.global [%0], [%1], 16;" :: "r"(s), "l"(g));
}
__device__ __forceinline__ void ldsm4(u32& r0, u32& r1, u32& r2, u32& r3, u32 addr) {
    asm volatile("ldmatrix.sync.aligned.m8n8.x4.shared.b16 {%0,%1,%2,%3}, [%4];"
                 : "=r"(r0), "=r"(r1), "=r"(r2), "=r"(r3) : "r"(addr));
}
__device__ __forceinline__ void mma16816(float& d0, float& d1, float& d2, float& d3,
                                         u32 a0, u32 a1, u32 a2, u32 a3, u32 b0, u32 b1) {
    asm volatile(
        "mma.sync.aligned.m16n8k16.row.col.f32.f16.f16.f32 "
        "{%0,%1,%2,%3},{%4,%5,%6,%7},{%8,%9},{%0,%1,%2,%3};"
        : "+f"(d0), "+f"(d1), "+f"(d2), "+f"(d3)
        : "r"(a0), "r"(a1), "r"(a2), "r"(a3), "r"(b0), "r"(b1));
}

// ---------------- problem constants ----------------
static constexpr int M_TOTAL = 8192;
static constexpr int N_TOTAL = 4096;
static constexpr int K_TOTAL = 4096;
static constexpr int BM = 128, BN = 256, BK = 64;
static constexpr int NCHUNK = K_TOTAL / BK;           // 64
static constexpr int NSTAGE = 4;
static constexpr u32 A_BYTES = BM * BK * 2;           // 16384
static constexpr u32 B_BYTES = BN * BK * 2;           // 32768
static constexpr u32 STAGE_BYTES = A_BYTES + B_BYTES; // 49152
static constexpr u32 SMEM_GEMM = NSTAGE * STAGE_BYTES; // 196608

// ---------------- prep kernels ----------------
__global__ void k_reset() { g_amax_bits = 0u; }

__global__ void k_amax(const float* __restrict__ w, int n) {
    float m = 0.f;
    for (int i = blockIdx.x * blockDim.x + threadIdx.x; i < n; i += gridDim.x * blockDim.x)
        m = fmaxf(m, fabsf(w[i]));
#pragma unroll
    for (int o = 16; o; o >>= 1) m = fmaxf(m, __shfl_xor_sync(0xffffffffu, m, o));
    if ((threadIdx.x & 31) == 0) atomicMax(&g_amax_bits, __float_as_uint(m));
}

__device__ __forceinline__ __half quant_one(float w, float scale) {
    float s = __fdiv_rn(w, scale);
    s = fminf(fmaxf(s, -240.f), 240.f);
    s = __half2float(__float2half_rn(s));        // fp16 round trip
    float q = rintf(s * 8.f) * 0.125f;           // round-half-even, 3-bit mantissa step
    q = fminf(fmaxf(q, -240.f), 240.f);
    return __float2half_rn(q);                   // exact (q fits fp16)
}

__global__ void k_quant(const float4* __restrict__ w, int n4) {
    float amax = __uint_as_float(g_amax_bits);
    float scale = fmaxf(amax / 240.f, 1e-10f);
    uint2* q2 = reinterpret_cast<uint2*>(g_q);
    for (int i = blockIdx.x * blockDim.x + threadIdx.x; i < n4; i += gridDim.x * blockDim.x) {
        float4 v = w[i];
        __half2 a = __halves2half2(quant_one(v.x, scale), quant_one(v.y, scale));
        __half2 b = __halves2half2(quant_one(v.z, scale), quant_one(v.w, scale));
        uint2 u;
        u.x = reinterpret_cast<const u32&>(a);
        u.y = reinterpret_cast<const u32&>(b);
        q2[i] = u;
    }
}

__global__ void k_xconv(const float4* __restrict__ x, int n4) {
    uint2* o2 = reinterpret_cast<uint2*>(g_xh);
    for (int i = blockIdx.x * blockDim.x + threadIdx.x; i < n4; i += gridDim.x * blockDim.x) {
        float4 v = x[i];
        __half2 a = __floats2half2_rn(v.x, v.y);
        __half2 b = __floats2half2_rn(v.z, v.w);
        uint2 u;
        u.x = reinterpret_cast<const u32&>(a);
        u.y = reinterpret_cast<const u32&>(b);
        o2[i] = u;
    }
}

// ---------------- HMMA GEMM ----------------
// grid (N/256=16, M/128=64) = 1024 CTAs; 512 threads; warp grid 2(M) x 8(N), warp tile 64x32.
__global__ void __launch_bounds__(512, 1)
k_gemm(const float* __restrict__ bias, float* __restrict__ out) {
    extern __shared__ __align__(1024) char smem[];
    const int tid = threadIdx.x;
    const int lane = tid & 31;
    const int wid = tid >> 5;
    const int warp_m = wid & 1;          // 0..1  -> 64 rows each
    const int warp_n = wid >> 1;         // 0..7  -> 32 cols each
    const u32 sbase = smem_u32(smem);

    const int tileM = blockIdx.y * BM;
    const int tileN = blockIdx.x * BN;

    // ---- cp.async load mapping (row = idx>>3, 16B chunk = idx&7) ----
    const char* gA = (const char*)g_xh + (size_t)tileM * (K_TOTAL * 2);
    const char* gB = (const char*)g_q  + (size_t)tileN * (K_TOTAL * 2);
    const char* gAp[2]; const char* gBp[4];
    u32 sA[2], sB[4];
#pragma unroll
    for (int j = 0; j < 2; j++) {
        int idx = tid + 512 * j;
        int row = idx >> 3, ch = idx & 7;
        gAp[j] = gA + (size_t)row * (K_TOTAL * 2) + ch * 16;
        u32 o = (u32)row * 128u + (u32)ch * 16u;
        sA[j] = o ^ ((o >> 3) & 0x70);
    }
#pragma unroll
    for (int j = 0; j < 4; j++) {
        int idx = tid + 512 * j;
        int row = idx >> 3, ch = idx & 7;
        gBp[j] = gB + (size_t)row * (K_TOTAL * 2) + ch * 16;
        u32 o = (u32)row * 128u + (u32)ch * 16u;
        sB[j] = (o ^ ((o >> 3) & 0x70)) + A_BYTES;
    }

    // ---- ldmatrix address precompute ----
    // A (x4): lanes 0-15 -> rows mrow+(l&15) col k ; lanes 16-31 -> same rows col k+8
    const int lrA = lane & 15;
    const u32 lcA = (u32)((lane >> 4) << 4);     // col byte offset part
    u32 rowrelA[4], maskA[4];
#pragma unroll
    for (int mf = 0; mf < 4; mf++) {
        int r = warp_m * 64 + mf * 16 + lrA;
        rowrelA[mf] = (u32)r * 128u;
        maskA[mf] = (u32)(r & 7) << 4;
    }
    // B (x4): lanes 0-7 -> n rows nb+(l&7), k ; 8-15 -> same rows, k+8 ; 16-31 -> rows +8
    const int lrB = (lane & 7) + ((lane & 16) >> 1);
    const u32 lcB = (u32)((lane & 8) << 1);
    u32 rowrelB[2], maskB[2];
#pragma unroll
    for (int bp = 0; bp < 2; bp++) {
        int r = warp_n * 32 + bp * 16 + lrB;
        rowrelB[bp] = A_BYTES + (u32)r * 128u;
        maskB[bp] = (u32)(r & 7) << 4;
    }

    float acc[4][4][4];
#pragma unroll
    for (int mf = 0; mf < 4; mf++)
#pragma unroll
        for (int nf = 0; nf < 4; nf++)
#pragma unroll
            for (int e = 0; e < 4; e++) acc[mf][nf][e] = 0.f;

    // ---- prologue: stages 0..2 ----
#pragma unroll
    for (int kc = 0; kc < 3; kc++) {
        u32 st = sbase + (u32)kc * STAGE_BYTES;
        size_t koff = (size_t)kc * 128;
#pragma unroll
        for (int j = 0; j < 2; j++) cp_async16(st + sA[j], gAp[j] + koff);
#pragma unroll
        for (int j = 0; j < 4; j++) cp_async16(st + sB[j], gBp[j] + koff);
        asm volatile("cp.async.commit_group;");
    }

    // ---- main loop ----
#pragma unroll 1
    for (int i = 0; i < NCHUNK; i++) {
        asm volatile("cp.async.wait_group 2;");
        __syncthreads();

        if (i + 3 < NCHUNK) {
            u32 st = sbase + (u32)((i + 3) & 3) * STAGE_BYTES;
            size_t koff = (size_t)(i + 3) * 128;
#pragma unroll
            for (int j = 0; j < 2; j++) cp_async16(st + sA[j], gAp[j] + koff);
#pragma unroll
            for (int j = 0; j < 4; j++) cp_async16(st + sB[j], gBp[j] + koff);
        }
        asm volatile("cp.async.commit_group;");

        const u32 st = sbase + (u32)(i & 3) * STAGE_BYTES;
#pragma unroll
        for (int ks = 0; ks < 4; ks++) {
            u32 a[4][4], b[2][4];
            const u32 colA = (u32)(ks * 32) + lcA;
            const u32 colB = (u32)(ks * 32) + lcB;
#pragma unroll
            for (int mf = 0; mf < 4; mf++)
                ldsm4(a[mf][0], a[mf][1], a[mf][2], a[mf][3],
                      st + rowrelA[mf] + (colA ^ maskA[mf]));
#pragma unroll
            for (int bp = 0; bp < 2; bp++)
                ldsm4(b[bp][0], b[bp][1], b[bp][2], b[bp][3],
                      st + rowrelB[bp] + (colB ^ maskB[bp]));
#pragma unroll
            for (int mf = 0; mf < 4; mf++) {
#pragma unroll
                for (int nf = 0; nf < 4; nf++) {
                    const u32 b0 = b[nf >> 1][(nf & 1) ? 2 : 0];
                    const u32 b1 = b[nf >> 1][(nf & 1) ? 3 : 1];
                    mma16816(acc[mf][nf][0], acc[mf][nf][1], acc[mf][nf][2], acc[mf][nf][3],
                             a[mf][0], a[mf][1], a[mf][2], a[mf][3], b0, b1);
                }
            }
        }
    }

    // ---- epilogue: direct float2 stores (32B-sector friendly) ----
    const float scale = fmaxf(__uint_as_float(g_amax_bits) / 240.f, 1e-10f);
#pragma unroll
    for (int mf = 0; mf < 4; mf++) {
        const int r0 = tileM + warp_m * 64 + mf * 16 + (lane >> 2);
#pragma unroll
        for (int nf = 0; nf < 4; nf++) {
            const int c = tileN + warp_n * 32 + nf * 8 + ((lane & 3) << 1);
            const float2 bv = *(const float2*)(bias + c);
            float2 o0, o1;
            o0.x = fmaf(acc[mf][nf][0], scale, bv.x);
            o0.y = fmaf(acc[mf][nf][1], scale, bv.y);
            o1.x = fmaf(acc[mf][nf][2], scale, bv.x);
            o1.y = fmaf(acc[mf][nf][3], scale, bv.y);
            *(float2*)(out + (size_t)r0 * N_TOTAL + c) = o0;
            *(float2*)(out + (size_t)(r0 + 8) * N_TOTAL + c) = o1;
        }
    }
}

// ---------------- launcher ----------------
extern "C" void kernel_launch(void* const* d_in, const int* in_sizes, int n_in,
                              void* d_out, int out_size) {
    const float* x    = (const float*)d_in[0];   // [4,2048,4096]
    const float* w    = (const float*)d_in[1];   // [4096,4096]
    const float* bias = (const float*)d_in[2];   // [4096]
    float* out = (float*)d_out;

    k_reset<<<1, 1>>>();
    k_amax<<<2048, 256>>>(w, N_TOTAL * K_TOTAL);
    k_quant<<<2048, 256>>>((const float4*)w, (N_TOTAL * K_TOTAL) / 4);
    k_xconv<<<4096, 256>>>((const float4*)x, (M_TOTAL * K_TOTAL) / 4);

    cudaFuncSetAttribute(k_gemm, cudaFuncAttributeMaxDynamicSharedMemorySize, SMEM_GEMM);
    dim3 grid(N_TOTAL / BN, M_TOTAL / BM, 1);    // (16, 64)
    k_gemm<<<grid, 512, SMEM_GEMM>>>(bias, out);
}

// round 4
// speedup vs baseline: 1.1271x; 1.1271x over previous
#include <cuda_runtime.h>
#include <cuda_fp16.h>

typedef unsigned int u32;

// ---------------- static device scratch (sanctioned) ----------------
__device__ u32 g_amax_bits;
__device__ __align__(16) __half g_q [4096u * 4096u];   // quantized weight [N,K], fp16 (exact)
__device__ __align__(16) __half g_xh[8192u * 4096u];   // x in fp16, [M,K]

// ---------------- helpers ----------------
__device__ __forceinline__ u32 smem_u32(const void* p) {
    u32 a;
    asm("{ .reg .u64 t; cvta.to.shared.u64 t, %1; cvt.u32.u64 %0, t; }" : "=r"(a) : "l"(p));
    return a;
}
__device__ __forceinline__ void cp_async16(u32 s, const void* g) {
    asm volatile("cp.async.cg.shared.global [%0], [%1], 16;" :: "r"(s), "l"(g));
}
__device__ __forceinline__ void ldsm4(u32& r0, u32& r1, u32& r2, u32& r3, u32 addr) {
    asm volatile("ldmatrix.sync.aligned.m8n8.x4.shared.b16 {%0,%1,%2,%3}, [%4];"
                 : "=r"(r0), "=r"(r1), "=r"(r2), "=r"(r3) : "r"(addr));
}
__device__ __forceinline__ void mma16816(float& d0, float& d1, float& d2, float& d3,
                                         u32 a0, u32 a1, u32 a2, u32 a3, u32 b0, u32 b1) {
    asm volatile(
        "mma.sync.aligned.m16n8k16.row.col.f32.f16.f16.f32 "
        "{%0,%1,%2,%3},{%4,%5,%6,%7},{%8,%9},{%0,%1,%2,%3};"
        : "+f"(d0), "+f"(d1), "+f"(d2), "+f"(d3)
        : "r"(a0), "r"(a1), "r"(a2), "r"(a3), "r"(b0), "r"(b1));
}

// ---------------- problem constants ----------------
static constexpr int M_TOTAL = 8192;
static constexpr int N_TOTAL = 4096;
static constexpr int K_TOTAL = 4096;
static constexpr int BM = 128, BN = 128, BK = 64;
static constexpr int NCHUNK = K_TOTAL / BK;            // 64
static constexpr u32 A_BYTES = BM * BK * 2;            // 16384
static constexpr u32 B_BYTES = BN * BK * 2;            // 16384
static constexpr u32 STAGE_BYTES = A_BYTES + B_BYTES;  // 32768
static constexpr int NSTAGE = 3;
static constexpr u32 SMEM_GEMM = NSTAGE * STAGE_BYTES; // 98304 -> 2 CTAs/SM

// ---------------- prep kernels ----------------
__global__ void k_reset() { g_amax_bits = 0u; }

__global__ void k_amax(const float4* __restrict__ w, int n4) {
    float m = 0.f;
    for (int i = blockIdx.x * blockDim.x + threadIdx.x; i < n4; i += gridDim.x * blockDim.x) {
        float4 v = w[i];
        m = fmaxf(m, fmaxf(fmaxf(fabsf(v.x), fabsf(v.y)), fmaxf(fabsf(v.z), fabsf(v.w))));
    }
#pragma unroll
    for (int o = 16; o; o >>= 1) m = fmaxf(m, __shfl_xor_sync(0xffffffffu, m, o));
    if ((threadIdx.x & 31) == 0) atomicMax(&g_amax_bits, __float_as_uint(m));
}

__device__ __forceinline__ __half quant_one(float w, float scale) {
    float s = __fdiv_rn(w, scale);
    s = fminf(fmaxf(s, -240.f), 240.f);
    s = __half2float(__float2half_rn(s));        // fp16 round trip
    float q = rintf(s * 8.f) * 0.125f;           // round-half-even, 3-bit mantissa step
    q = fminf(fmaxf(q, -240.f), 240.f);
    return __float2half_rn(q);                   // exact (q fits fp16)
}

__global__ void k_quant(const float4* __restrict__ w, int n4) {
    float amax = __uint_as_float(g_amax_bits);
    float scale = fmaxf(amax / 240.f, 1e-10f);
    uint2* q2 = reinterpret_cast<uint2*>(g_q);
    for (int i = blockIdx.x * blockDim.x + threadIdx.x; i < n4; i += gridDim.x * blockDim.x) {
        float4 v = w[i];
        __half2 a = __halves2half2(quant_one(v.x, scale), quant_one(v.y, scale));
        __half2 b = __halves2half2(quant_one(v.z, scale), quant_one(v.w, scale));
        uint2 u;
        u.x = reinterpret_cast<const u32&>(a);
        u.y = reinterpret_cast<const u32&>(b);
        q2[i] = u;
    }
}

__global__ void k_xconv(const float4* __restrict__ x, int n4) {
    uint2* o2 = reinterpret_cast<uint2*>(g_xh);
    for (int i = blockIdx.x * blockDim.x + threadIdx.x; i < n4; i += gridDim.x * blockDim.x) {
        float4 v = x[i];
        __half2 a = __floats2half2_rn(v.x, v.y);
        __half2 b = __floats2half2_rn(v.z, v.w);
        uint2 u;
        u.x = reinterpret_cast<const u32&>(a);
        u.y = reinterpret_cast<const u32&>(b);
        o2[i] = u;
    }
}

// ---------------- HMMA GEMM, 2 CTAs/SM ----------------
// grid (N/128=32, M/128=64) = 2048 CTAs; 256 threads; warp grid 2(M) x 4(N), warp tile 64x32.
__global__ void __launch_bounds__(256, 2)
k_gemm(const float* __restrict__ bias, float* __restrict__ out) {
    extern __shared__ __align__(1024) char smem[];
    const int tid = threadIdx.x;
    const int lane = tid & 31;
    const int wid = tid >> 5;
    const int warp_m = wid & 1;           // 0..1 -> 64 rows each
    const int warp_n = wid >> 1;          // 0..3 -> 32 cols each
    const u32 sbase = smem_u32(smem);

    const int tileM = blockIdx.y * BM;
    const int tileN = blockIdx.x * BN;

    // ---- cp.async mapping: thread -> row0=tid>>3 (+32 per rep), 16B chunk tid&7 ----
    const int row0 = tid >> 3, ch = tid & 7;
    const char* gA0 = (const char*)g_xh + ((size_t)(tileM + row0)) * (K_TOTAL * 2) + ch * 16;
    const char* gB0 = (const char*)g_q  + ((size_t)(tileN + row0)) * (K_TOTAL * 2) + ch * 16;
    u32 o0 = (u32)row0 * 128u + (u32)ch * 16u;
    const u32 sA0 = o0 ^ ((o0 >> 3) & 0x70);           // +4096*j per rep (swizzle-safe)
    const u32 sB0 = sA0 + A_BYTES;
    constexpr size_t GROW = 32ull * K_TOTAL * 2;       // 32 rows in gmem

    // ---- ldmatrix address precompute ----
    const int lrA = lane & 15;
    const u32 lcA = (u32)((lane >> 4) << 4);
    u32 rA[4], mAk[4];
#pragma unroll
    for (int mf = 0; mf < 4; mf++) {
        int r = warp_m * 64 + mf * 16 + lrA;
        rA[mf] = (u32)r * 128u;
        mAk[mf] = (u32)(r & 7) << 4;
    }
    const int lrB = (lane & 7) + ((lane & 16) >> 1);
    const u32 lcB = (u32)((lane & 8) << 1);
    u32 rB[2], mBk[2];
#pragma unroll
    for (int bp = 0; bp < 2; bp++) {
        int r = warp_n * 32 + bp * 16 + lrB;
        rB[bp] = A_BYTES + (u32)r * 128u;
        mBk[bp] = (u32)(r & 7) << 4;
    }

    float acc[4][4][4];
#pragma unroll
    for (int mf = 0; mf < 4; mf++)
#pragma unroll
        for (int nf = 0; nf < 4; nf++)
#pragma unroll
            for (int e = 0; e < 4; e++) acc[mf][nf][e] = 0.f;

    // ---- prologue: chunks 0,1 -> stages 0,1 ----
#pragma unroll
    for (int kc = 0; kc < 2; kc++) {
        u32 st = sbase + (u32)kc * STAGE_BYTES;
        size_t koff = (size_t)kc * 128;
#pragma unroll
        for (int j = 0; j < 4; j++) {
            cp_async16(st + sA0 + 4096u * j, gA0 + koff + GROW * j);
            cp_async16(st + sB0 + 4096u * j, gB0 + koff + GROW * j);
        }
        asm volatile("cp.async.commit_group;");
    }

    u32 a[2][4][4], b[2][4];

    // ---- main loop ----
#pragma unroll 1
    for (int i = 0; i < NCHUNK; i++) {
        asm volatile("cp.async.wait_group 1;");
        __syncthreads();

        if (i + 2 < NCHUNK) {
            u32 st = sbase + (u32)((i + 2) % 3) * STAGE_BYTES;
            size_t koff = (size_t)(i + 2) * 128;
#pragma unroll
            for (int j = 0; j < 4; j++) {
                cp_async16(st + sA0 + 4096u * j, gA0 + koff + GROW * j);
                cp_async16(st + sB0 + 4096u * j, gB0 + koff + GROW * j);
            }
        }
        asm volatile("cp.async.commit_group;");

        const u32 st = sbase + (u32)(i % 3) * STAGE_BYTES;

        // preload A frags for ks=0
#pragma unroll
        for (int mf = 0; mf < 4; mf++)
            ldsm4(a[0][mf][0], a[0][mf][1], a[0][mf][2], a[0][mf][3],
                  st + rA[mf] + (lcA ^ mAk[mf]));

#pragma unroll
        for (int ks = 0; ks < 4; ks++) {
            const int cur = ks & 1;
            // prefetch A frags for ks+1
            if (ks < 3) {
                const u32 colA = (u32)((ks + 1) * 32) + lcA;
#pragma unroll
                for (int mf = 0; mf < 4; mf++)
                    ldsm4(a[cur ^ 1][mf][0], a[cur ^ 1][mf][1], a[cur ^ 1][mf][2], a[cur ^ 1][mf][3],
                          st + rA[mf] + (colA ^ mAk[mf]));
            }
            // B frags for this ks (single-buffered; hidden under tensor-pipe backlog)
            {
                const u32 colB = (u32)(ks * 32) + lcB;
#pragma unroll
                for (int bp = 0; bp < 2; bp++)
                    ldsm4(b[bp][0], b[bp][1], b[bp][2], b[bp][3],
                          st + rB[bp] + (colB ^ mBk[bp]));
            }
#pragma unroll
            for (int mf = 0; mf < 4; mf++) {
#pragma unroll
                for (int nf = 0; nf < 4; nf++) {
                    const u32 b0 = b[nf >> 1][(nf & 1) ? 2 : 0];
                    const u32 b1 = b[nf >> 1][(nf & 1) ? 3 : 1];
                    mma16816(acc[mf][nf][0], acc[mf][nf][1], acc[mf][nf][2], acc[mf][nf][3],
                             a[cur][mf][0], a[cur][mf][1], a[cur][mf][2], a[cur][mf][3], b0, b1);
                }
            }
        }
    }

    // ---- epilogue: direct float2 stores ----
    const float scale = fmaxf(__uint_as_float(g_amax_bits) / 240.f, 1e-10f);
#pragma unroll
    for (int mf = 0; mf < 4; mf++) {
        const int r0 = tileM + warp_m * 64 + mf * 16 + (lane >> 2);
#pragma unroll
        for (int nf = 0; nf < 4; nf++) {
            const int c = tileN + warp_n * 32 + nf * 8 + ((lane & 3) << 1);
            const float2 bv = *(const float2*)(bias + c);
            float2 o0, o1;
            o0.x = fmaf(acc[mf][nf][0], scale, bv.x);
            o0.y = fmaf(acc[mf][nf][1], scale, bv.y);
            o1.x = fmaf(acc[mf][nf][2], scale, bv.x);
            o1.y = fmaf(acc[mf][nf][3], scale, bv.y);
            *(float2*)(out + (size_t)r0 * N_TOTAL + c) = o0;
            *(float2*)(out + (size_t)(r0 + 8) * N_TOTAL + c) = o1;
        }
    }
}

// ---------------- launcher ----------------
extern "C" void kernel_launch(void* const* d_in, const int* in_sizes, int n_in,
                              void* d_out, int out_size) {
    const float* x    = (const float*)d_in[0];   // [4,2048,4096]
    const float* w    = (const float*)d_in[1];   // [4096,4096]
    const float* bias = (const float*)d_in[2];   // [4096]
    float* out = (float*)d_out;

    k_reset<<<1, 1>>>();
    k_amax<<<2048, 256>>>((const float4*)w, (N_TOTAL * K_TOTAL) / 4);
    k_quant<<<2048, 256>>>((const float4*)w, (N_TOTAL * K_TOTAL) / 4);
    k_xconv<<<4096, 256>>>((const float4*)x, (M_TOTAL * K_TOTAL) / 4);

    cudaFuncSetAttribute(k_gemm, cudaFuncAttributeMaxDynamicSharedMemorySize, SMEM_GEMM);
    dim3 grid(N_TOTAL / BN, M_TOTAL / BM, 1);    // (32, 64)
    k_gemm<<<grid, 256, SMEM_GEMM>>>(bias, out);
}